// round 12
// baseline (speedup 1.0000x reference)
#include <cuda_runtime.h>
#include <math.h>
#include <stdint.h>

constexpr int Bb   = 2;
constexpr int Hh   = 16;
constexpr int Nn   = 2048;
constexpr int HDc  = 64;
constexpr int DIMd = 1024;
constexpr int Mrows = Bb * Nn;       // 4096
constexpr float ATTN_SCALE = 0.125f;

// k-group permutation: storage position 2t holds logical k t, 2t+1 holds t+4.
// Applied to every contraction dimension so mma fragments load as 64-bit pairs.

// Scratch buffers
__device__ float g_qh[Bb * Hh * Nn * HDc];   // Q heads (tf32, perm head dim, pre-scaled)
__device__ float g_kh[Bb * Hh * Nn * HDc];   // K heads (tf32, perm head dim)
__device__ float g_vh[Bb * Hh * Nn * HDc];   // V heads (tf32, perm head dim)
__device__ float g_ao[Bb * Hh * Nn * HDc];   // attn out (tf32, perm head dim)
__device__ float g_qt[Mrows * DIMd];         // tf32 perm-k copies of inputs
__device__ float g_kt[Mrows * DIMd];
__device__ float g_vt[Mrows * DIMd];
__device__ float g_wq[DIMd * DIMd];          // tf32 perm-k copies of weights
__device__ float g_wk[DIMd * DIMd];
__device__ float g_wv[DIMd * DIMd];
__device__ float g_wo[DIMd * DIMd];

__device__ __forceinline__ uint32_t tf32r(float x) {
    uint32_t y;
    asm("cvt.rna.tf32.f32 %0, %1;" : "=r"(y) : "f"(x));
    return y;
}

__device__ __forceinline__ void mma8(float* d, const uint32_t* a, const uint32_t* b) {
    asm volatile(
        "mma.sync.aligned.m16n8k8.row.col.f32.tf32.tf32.f32 "
        "{%0,%1,%2,%3}, {%4,%5,%6,%7}, {%8,%9}, {%0,%1,%2,%3};\n"
        : "+f"(d[0]), "+f"(d[1]), "+f"(d[2]), "+f"(d[3])
        : "r"(a[0]), "r"(a[1]), "r"(a[2]), "r"(a[3]), "r"(b[0]), "r"(b[1]));
}

__device__ __forceinline__ void cp16(uint32_t daddr, const void* src) {
    asm volatile("cp.async.cg.shared.global [%0], [%1], 16;\n"
                 :: "r"(daddr), "l"(src));
}
__device__ __forceinline__ void cp_commit() {
    asm volatile("cp.async.commit_group;\n");
}
template <int N>
__device__ __forceinline__ void cp_wait() {
    asm volatile("cp.async.wait_group %0;\n" :: "n"(N));
}

// ---------------------------------------------------------------------------
// Fused tf32 (RNA) conversion + k-group permute (one launch).
// Each thread handles one 8-wide k-group: out = {in0,in4,in1,in5,in2,in6,in3,in7}.
// ---------------------------------------------------------------------------
__global__ __launch_bounds__(256) void cvt_all(
    const float4* q, const float4* k, const float4* v,
    const float4* wq, const float4* wk, const float4* wv, const float4* wo,
    float4* qt, float4* kt, float4* vt,
    float4* dwq, float4* dwk, float4* dwv, float4* dwo)
{
    const int z = blockIdx.z;
    const int n8 = (z < 3) ? (Mrows * DIMd / 8) : (DIMd * DIMd / 8);
    const int i = blockIdx.x * 256 + threadIdx.x;
    if (i >= n8) return;
    const float4* s;
    float4* d;
    switch (z) {
        case 0: s = q;  d = qt;  break;
        case 1: s = k;  d = kt;  break;
        case 2: s = v;  d = vt;  break;
        case 3: s = wq; d = dwq; break;
        case 4: s = wk; d = dwk; break;
        case 5: s = wv; d = dwv; break;
        default: s = wo; d = dwo; break;
    }
    const float4 a = s[2 * i];       // logical k 0..3
    const float4 b = s[2 * i + 1];   // logical k 4..7
    float4 o0, o1;
    o0.x = __uint_as_float(tf32r(a.x)); o0.y = __uint_as_float(tf32r(b.x));
    o0.z = __uint_as_float(tf32r(a.y)); o0.w = __uint_as_float(tf32r(b.y));
    o1.x = __uint_as_float(tf32r(a.z)); o1.y = __uint_as_float(tf32r(b.z));
    o1.z = __uint_as_float(tf32r(a.w)); o1.w = __uint_as_float(tf32r(b.w));
    d[2 * i]     = o0;
    d[2 * i + 1] = o1;
}

// ---------------------------------------------------------------------------
// Projection GEMM: 128x128x32 tiles, 2-stage cp.async double buffer,
// 81.9KB smem, __launch_bounds__(256,2) -> 2 CTAs/SM. ONE barrier per k-iter:
// {wait<0>; sync; issue(kt+1); mma} — prefetch still overlaps compute.
// ---------------------------------------------------------------------------
constexpr int SKA = 40;                        // smem k-stride words
constexpr int PROJ_SMEM = 4 * 128 * SKA * 4;   // 81920 B

template <bool SPLIT_IN, bool SPLIT_OUT, bool ROUND>
__device__ __forceinline__ void proj_body(
    const float* __restrict__ A, const float* __restrict__ W,
    const float* __restrict__ bias, float* __restrict__ C, float scale,
    float* smf)
{
    const int m0 = blockIdx.y * 128, n0 = blockIdx.x * 128;
    const int tid = threadIdx.x;
    const int w = tid >> 5, lane = tid & 31;
    const int gid = lane >> 2, tig = lane & 3;
    const int mbase = (w & 1) * 64;
    const int nbase = (w >> 1) * 32;

    const uint32_t* Asb[2] = {(const uint32_t*)smf,
                              (const uint32_t*)smf + 128 * SKA};
    const uint32_t* Wsb[2] = {(const uint32_t*)smf + 2 * 128 * SKA,
                              (const uint32_t*)smf + 3 * 128 * SKA};
    const uint32_t su = (uint32_t)__cvta_generic_to_shared(smf);
    const uint32_t asu[2] = {su, su + 128 * SKA * 4};
    const uint32_t wsu[2] = {su + 2 * 128 * SKA * 4, su + 3 * 128 * SKA * 4};

    auto load_tiles = [&](int kt, int buf) {
        const int k0 = kt * 32;
#pragma unroll
        for (int t = 0; t < 4; t++) {
            const int idx = tid + t * 256;
            const int r = idx >> 3, c = (idx & 7) << 2;
            const float* ap;
            if (SPLIT_IN) {
                const int gm = m0 + r, gk = k0 + c;
                const int b = gm >> 11, tok = gm & (Nn - 1);
                const int h = gk >> 6, cc = gk & 63;
                ap = A + ((size_t)((b * Hh + h) * Nn + tok)) * HDc + cc;
            } else {
                ap = A + (size_t)(m0 + r) * DIMd + k0 + c;
            }
            cp16(asu[buf] + (r * SKA + c) * 4, ap);
            cp16(wsu[buf] + (r * SKA + c) * 4,
                 W + (size_t)(n0 + r) * DIMd + k0 + c);
        }
        cp_commit();
    };

    float c[4][4][4];
#pragma unroll
    for (int mi = 0; mi < 4; mi++)
#pragma unroll
        for (int ni = 0; ni < 4; ni++)
#pragma unroll
            for (int u = 0; u < 4; u++) c[mi][ni][u] = 0.f;

    load_tiles(0, 0);
    constexpr int ITERS = DIMd / 32;  // 32
    for (int kt = 0; kt < ITERS; kt++) {
        const int cur = kt & 1;
        cp_wait<0>();      // tile kt resident (kt+1 not yet issued)
        __syncthreads();   // visibility + all warps past kt-1 reads of buf^1
        if (kt + 1 < ITERS) load_tiles(kt + 1, cur ^ 1);  // overlaps mma below

        const uint32_t* Ab = Asb[cur];
        const uint32_t* Wb = Wsb[cur];
#pragma unroll
        for (int kk = 0; kk < 32; kk += 8) {
            uint32_t af[4][4];
#pragma unroll
            for (int mi = 0; mi < 4; mi++) {
                const int row = mbase + mi * 16 + gid;
                const uint2 a0 = *reinterpret_cast<const uint2*>(
                    Ab + row * SKA + kk + 2 * tig);
                const uint2 a1 = *reinterpret_cast<const uint2*>(
                    Ab + (row + 8) * SKA + kk + 2 * tig);
                af[mi][0] = a0.x; af[mi][1] = a1.x;
                af[mi][2] = a0.y; af[mi][3] = a1.y;
            }
            uint32_t bf[4][2];
#pragma unroll
            for (int ni = 0; ni < 4; ni++) {
                const uint2 b = *reinterpret_cast<const uint2*>(
                    Wb + (nbase + ni * 8 + gid) * SKA + kk + 2 * tig);
                bf[ni][0] = b.x;
                bf[ni][1] = b.y;
            }
#pragma unroll
            for (int mi = 0; mi < 4; mi++)
#pragma unroll
                for (int ni = 0; ni < 4; ni++)
                    mma8(c[mi][ni], af[mi], bf[ni]);
        }
    }

    // Epilogue. Logical cols 2tig, 2tig+1 -> permuted head positions p0, p0+2.
    const int p0 = (tig < 2) ? 4 * tig : 4 * tig - 7;
#pragma unroll
    for (int mi = 0; mi < 4; mi++) {
#pragma unroll
        for (int ni = 0; ni < 4; ni++) {
            const int nlog = n0 + nbase + ni * 8 + 2 * tig;
            const float bx = bias[nlog], by = bias[nlog + 1];
#pragma unroll
            for (int hr = 0; hr < 2; hr++) {
                const int m = m0 + mbase + mi * 16 + gid + hr * 8;
                float ox = (c[mi][ni][hr * 2 + 0] + bx) * scale;
                float oy = (c[mi][ni][hr * 2 + 1] + by) * scale;
                if (ROUND) {
                    ox = __uint_as_float(tf32r(ox));
                    oy = __uint_as_float(tf32r(oy));
                }
                if (SPLIT_OUT) {
                    const int b = m >> 11, tok = m & (Nn - 1);
                    const int np0 = n0 + nbase + ni * 8 + p0;
                    const int h = np0 >> 6;
                    float* dst = C + ((size_t)((b * Hh + h) * Nn + tok)) * HDc;
                    dst[np0 & 63]       = ox;
                    dst[(np0 + 2) & 63] = oy;
                } else {
                    float2 o; o.x = ox; o.y = oy;
                    *reinterpret_cast<float2*>(C + (size_t)m * DIMd + nlog) = o;
                }
            }
        }
    }
}

__global__ __launch_bounds__(256, 2) void qkv_proj(
    const float* aq, const float* ak, const float* av,
    const float* wq, const float* wk, const float* wv,
    const float* bq, const float* bk, const float* bv,
    float* cq, float* ck, float* cv)
{
    extern __shared__ float smf[];
    const int z = blockIdx.z;
    const float* A = (z == 0) ? aq : (z == 1) ? ak : av;
    const float* W = (z == 0) ? wq : (z == 1) ? wk : wv;
    const float* b = (z == 0) ? bq : (z == 1) ? bk : bv;
    float*       C = (z == 0) ? cq : (z == 1) ? ck : cv;
    const float scale = (z == 0) ? ATTN_SCALE : 1.0f;
    proj_body<false, true, true>(A, W, b, C, scale, smf);
}

__global__ __launch_bounds__(256, 2) void o_proj(
    const float* A, const float* W, const float* b, float* C)
{
    extern __shared__ float smf[];
    proj_body<true, false, false>(A, W, b, C, 1.0f, smf);
}

// ---------------------------------------------------------------------------
// Causal flash attention: 64 q-rows/CTA, 128 threads (4 warps, 16x64 strips),
// register softmax, heavy-first. ONE barrier per k-tile:
// {wait<0>; sync; issue(kt+1); S; softmax; PV} — prefetch overlaps compute.
// K token-major (perm head dim), P perm-token; LDS.64 frags (AST=72).
// ---------------------------------------------------------------------------
constexpr int AST = 72;  // smem row stride (words)
constexpr int ATT_SMEM = 5 * 64 * AST * 4;  // 2xK, 2xV, P = 92160 B

__global__ __launch_bounds__(128) void attn2(
    const float* __restrict__ Qg, const float* __restrict__ Kg,
    const float* __restrict__ Vg, float* __restrict__ Og)
{
    extern __shared__ float smf[];
    const uint32_t su = (uint32_t)__cvta_generic_to_shared(smf);
    const uint32_t ksu[2] = {su, su + 64 * AST * 4};
    const uint32_t vsu[2] = {su + 2 * 64 * AST * 4, su + 3 * 64 * AST * 4};
    const uint32_t* Ksb[2] = {(const uint32_t*)smf,
                              (const uint32_t*)smf + 64 * AST};
    const uint32_t* Vsb[2] = {(const uint32_t*)smf + 2 * 64 * AST,
                              (const uint32_t*)smf + 3 * 64 * AST};
    uint32_t* Psu = (uint32_t*)smf + 4 * 64 * AST;

    const int bh = blockIdx.y;
    const int qt = (gridDim.x - 1) - blockIdx.x;   // heavy-first
    const int q0 = qt * 64;
    const size_t base = (size_t)bh * Nn * HDc;

    const int tid = threadIdx.x;
    const int w = tid >> 5, lane = tid & 31;
    const int gid = lane >> 2, tig = lane & 3;
    const int mrow = w * 16;
    const int p0 = (tig < 2) ? 4 * tig : 4 * tig - 7;  // perm pos of col 2tig

    auto issueKV = [&](int t_kt, int buf) {
        const float* Kb = Kg + base + (size_t)(t_kt * 64) * HDc;
        const float* Vb = Vg + base + (size_t)(t_kt * 64) * HDc;
#pragma unroll
        for (int t = 0; t < 8; t++) {
            const int idx = tid + t * 128;
            const int r = idx >> 4, cc = (idx & 15) << 2;
            cp16(ksu[buf] + (r * AST + cc) * 4, Kb + r * HDc + cc);
            cp16(vsu[buf] + (r * AST + cc) * 4, Vb + r * HDc + cc);
        }
        cp_commit();
    };

    // Q fragments from perm-k qh: 64-bit pairs at 2tig
    uint32_t qf[8][4];
    {
        const uint32_t* Qu = (const uint32_t*)(Qg + base) +
                             (size_t)(q0 + mrow + gid) * HDc;
#pragma unroll
        for (int s = 0; s < 8; s++) {
            const uint2 u0 = *reinterpret_cast<const uint2*>(Qu + s * 8 + 2 * tig);
            const uint2 u1 = *reinterpret_cast<const uint2*>(Qu + 8 * HDc + s * 8 + 2 * tig);
            qf[s][0] = u0.x; qf[s][1] = u1.x;
            qf[s][2] = u0.y; qf[s][3] = u1.y;
        }
    }

    float o[8][4];
#pragma unroll
    for (int ni = 0; ni < 8; ni++)
#pragma unroll
        for (int u = 0; u < 4; u++) o[ni][u] = 0.f;
    float m0r = -1e30f, m1r = -1e30f, l0 = 0.f, l1 = 0.f;

    issueKV(0, 0);

    for (int kt = 0; kt <= qt; kt++) {
        const int cur = kt & 1;
        cp_wait<0>();      // tile kt resident (kt+1 not yet issued)
        __syncthreads();   // visibility + all warps past kt-1 reads of buf^1
        if (kt < qt) issueKV(kt + 1, cur ^ 1);  // overlaps compute below

        // ---- S = Q K^T (16x64 per warp); LDS.64 K frags ----
        float s4[8][4];
#pragma unroll
        for (int ni = 0; ni < 8; ni++)
#pragma unroll
            for (int u = 0; u < 4; u++) s4[ni][u] = 0.f;

        const uint32_t* Kb = Ksb[cur];
#pragma unroll
        for (int s = 0; s < 8; s++) {
            const int kk = s * 8;
            uint32_t bf[8][2];
#pragma unroll
            for (int ni = 0; ni < 8; ni++) {
                const uint2 b = *reinterpret_cast<const uint2*>(
                    Kb + (ni * 8 + gid) * AST + kk + 2 * tig);
                bf[ni][0] = b.x;
                bf[ni][1] = b.y;
            }
#pragma unroll
            for (int ni = 0; ni < 8; ni++)
                mma8(s4[ni], qf[s], bf[ni]);
        }

        // ---- causal mask (diagonal tile only) ----
        if (kt == qt) {
            const int r0 = q0 + mrow + gid, r1 = r0 + 8;
            const int k0 = kt * 64;
#pragma unroll
            for (int ni = 0; ni < 8; ni++) {
                const int cc = k0 + ni * 8 + 2 * tig;
                if (cc > r0)     s4[ni][0] = -1e30f;
                if (cc + 1 > r0) s4[ni][1] = -1e30f;
                if (cc > r1)     s4[ni][2] = -1e30f;
                if (cc + 1 > r1) s4[ni][3] = -1e30f;
            }
        }

        // ---- register softmax (rows warp-local; quad reduction) ----
        float mx0 = -1e30f, mx1 = -1e30f;
#pragma unroll
        for (int ni = 0; ni < 8; ni++) {
            mx0 = fmaxf(mx0, fmaxf(s4[ni][0], s4[ni][1]));
            mx1 = fmaxf(mx1, fmaxf(s4[ni][2], s4[ni][3]));
        }
        mx0 = fmaxf(mx0, __shfl_xor_sync(0xffffffffu, mx0, 1));
        mx0 = fmaxf(mx0, __shfl_xor_sync(0xffffffffu, mx0, 2));
        mx1 = fmaxf(mx1, __shfl_xor_sync(0xffffffffu, mx1, 1));
        mx1 = fmaxf(mx1, __shfl_xor_sync(0xffffffffu, mx1, 2));
        const float mn0 = fmaxf(m0r, mx0);
        const float mn1 = fmaxf(m1r, mx1);
        const float f0 = __expf(m0r - mn0);
        const float f1 = __expf(m1r - mn1);
        m0r = mn0; m1r = mn1;

        // P written at perm-token positions: col 2tig -> p0, 2tig+1 -> p0+2
        float sum0 = 0.f, sum1 = 0.f;
        uint32_t* PwA = Psu + (mrow + gid) * AST;
        uint32_t* PwB = PwA + 8 * AST;
#pragma unroll
        for (int ni = 0; ni < 8; ni++) {
            const float e0 = __expf(s4[ni][0] - mn0);
            const float e1 = __expf(s4[ni][1] - mn0);
            const float e2 = __expf(s4[ni][2] - mn1);
            const float e3 = __expf(s4[ni][3] - mn1);
            sum0 += e0 + e1;
            sum1 += e2 + e3;
            PwA[ni * 8 + p0]     = tf32r(e0);
            PwA[ni * 8 + p0 + 2] = tf32r(e1);
            PwB[ni * 8 + p0]     = tf32r(e2);
            PwB[ni * 8 + p0 + 2] = tf32r(e3);
        }
        sum0 += __shfl_xor_sync(0xffffffffu, sum0, 1);
        sum0 += __shfl_xor_sync(0xffffffffu, sum0, 2);
        sum1 += __shfl_xor_sync(0xffffffffu, sum1, 1);
        sum1 += __shfl_xor_sync(0xffffffffu, sum1, 2);
        l0 = l0 * f0 + sum0;
        l1 = l1 * f1 + sum1;

#pragma unroll
        for (int ni = 0; ni < 8; ni++) {
            o[ni][0] *= f0; o[ni][1] *= f0;
            o[ni][2] *= f1; o[ni][3] *= f1;
        }
        __syncwarp();

        // ---- O += P * V; P perm-token -> LDS.64 A-frags ----
        const uint32_t* Vb = Vsb[cur];
#pragma unroll
        for (int s = 0; s < 8; s++) {
            const int kk = s * 8;
            uint32_t af[4];
            const uint2 pa = *reinterpret_cast<const uint2*>(
                Psu + (mrow + gid) * AST + kk + 2 * tig);
            const uint2 pb = *reinterpret_cast<const uint2*>(
                Psu + (mrow + gid + 8) * AST + kk + 2 * tig);
            af[0] = pa.x; af[1] = pb.x;
            af[2] = pa.y; af[3] = pb.y;
            uint32_t bf[8][2];
#pragma unroll
            for (int ni = 0; ni < 8; ni++) {
                const uint32_t* q = Vb + (kk + tig) * AST + ni * 8 + gid;
                bf[ni][0] = q[0];
                bf[ni][1] = q[4 * AST];
            }
#pragma unroll
            for (int ni = 0; ni < 8; ni++)
                mma8(o[ni], af, bf[ni]);
        }
    }

    // ---- finalize (cols = perm head positions, matching o_proj input) ----
    {
        const float inv0 = 1.f / l0;
        const float inv1 = 1.f / l1;
        const int r0 = q0 + mrow + gid;
        uint32_t* Ou = (uint32_t*)(Og + base);
#pragma unroll
        for (int ni = 0; ni < 8; ni++) {
            const int cc = ni * 8 + 2 * tig;
            uint2 oa, ob;
            oa.x = tf32r(o[ni][0] * inv0);
            oa.y = tf32r(o[ni][1] * inv0);
            ob.x = tf32r(o[ni][2] * inv1);
            ob.y = tf32r(o[ni][3] * inv1);
            *reinterpret_cast<uint2*>(Ou + (size_t)r0 * HDc + cc) = oa;
            *reinterpret_cast<uint2*>(Ou + (size_t)(r0 + 8) * HDc + cc) = ob;
        }
    }
}

// ---------------------------------------------------------------------------
extern "C" void kernel_launch(void* const* d_in, const int* in_sizes, int n_in,
                              void* d_out, int out_size)
{
    const float* q  = (const float*)d_in[0];
    const float* k  = (const float*)d_in[1];
    const float* v  = (const float*)d_in[2];
    // d_in[3] = mask (tril; causality applied analytically)
    const float* Wq = (const float*)d_in[4];
    const float* bq = (const float*)d_in[5];
    const float* Wk = (const float*)d_in[6];
    const float* bk = (const float*)d_in[7];
    const float* Wv = (const float*)d_in[8];
    const float* bv = (const float*)d_in[9];
    const float* Wo = (const float*)d_in[10];
    const float* bo = (const float*)d_in[11];
    float* out = (float*)d_out;

    float *qh, *kh, *vh, *ao, *qt, *kt, *vt, *wq, *wk, *wv, *wo;
    cudaGetSymbolAddress((void**)&qh, g_qh);
    cudaGetSymbolAddress((void**)&kh, g_kh);
    cudaGetSymbolAddress((void**)&vh, g_vh);
    cudaGetSymbolAddress((void**)&ao, g_ao);
    cudaGetSymbolAddress((void**)&qt, g_qt);
    cudaGetSymbolAddress((void**)&kt, g_kt);
    cudaGetSymbolAddress((void**)&vt, g_vt);
    cudaGetSymbolAddress((void**)&wq, g_wq);
    cudaGetSymbolAddress((void**)&wk, g_wk);
    cudaGetSymbolAddress((void**)&wv, g_wv);
    cudaGetSymbolAddress((void**)&wo, g_wo);

    static int cfg = 0;
    if (!cfg) {
        cudaFuncSetAttribute(qkv_proj,
            cudaFuncAttributeMaxDynamicSharedMemorySize, PROJ_SMEM);
        cudaFuncSetAttribute(o_proj,
            cudaFuncAttributeMaxDynamicSharedMemorySize, PROJ_SMEM);
        cudaFuncSetAttribute(attn2,
            cudaFuncAttributeMaxDynamicSharedMemorySize, ATT_SMEM);
        cfg = 1;
    }

    // tf32 + perm-k conversion, one launch
    const int blocks_x = (Mrows * DIMd / 8 + 255) / 256;  // 2048
    cvt_all<<<dim3(blocks_x, 1, 7), 256>>>(
        (const float4*)q, (const float4*)k, (const float4*)v,
        (const float4*)Wq, (const float4*)Wk, (const float4*)Wv, (const float4*)Wo,
        (float4*)qt, (float4*)kt, (float4*)vt,
        (float4*)wq, (float4*)wk, (float4*)wv, (float4*)wo);

    // Fused QKV projections (Q pre-scaled by ATTN_SCALE in epilogue)
    qkv_proj<<<dim3(DIMd / 128, Mrows / 128, 3), 256, PROJ_SMEM>>>(
        qt, kt, vt, wq, wk, wv, bq, bk, bv, qh, kh, vh);

    // Attention: 64 q-rows per CTA, heavy tiles first
    attn2<<<dim3(Nn / 64, Bb * Hh), 128, ATT_SMEM>>>(qh, kh, vh, ao);

    // Output projection
    o_proj<<<dim3(DIMd / 128, Mrows / 128), 256, PROJ_SMEM>>>(ao, wo, bo, out);
}

// round 13
// speedup vs baseline: 1.0957x; 1.0957x over previous
#include <cuda_runtime.h>
#include <math.h>
#include <stdint.h>

constexpr int Bb   = 2;
constexpr int Hh   = 16;
constexpr int Nn   = 2048;
constexpr int HDc  = 64;
constexpr int DIMd = 1024;
constexpr int Mrows = Bb * Nn;       // 4096
constexpr float ATTN_SCALE = 0.125f;

// k-group permutation: storage position 2t holds logical k t, 2t+1 holds t+4.
// Applied to every contraction dimension so mma fragments load as 64-bit pairs.
// In attention, the K tile's token ROWS are also stored permuted, which makes
// S-output columns land in perm-token order => the PV A-fragment is a pure
// register rename of the softmax output (no P smem round-trip at all).

// Scratch buffers
__device__ float g_qh[Bb * Hh * Nn * HDc];   // Q heads (tf32, perm head dim, pre-scaled)
__device__ float g_kh[Bb * Hh * Nn * HDc];   // K heads (tf32, perm head dim)
__device__ float g_vh[Bb * Hh * Nn * HDc];   // V heads (tf32, perm head dim)
__device__ float g_ao[Bb * Hh * Nn * HDc];   // attn out (tf32, perm head dim)
__device__ float g_qt[Mrows * DIMd];         // tf32 perm-k copies of inputs
__device__ float g_kt[Mrows * DIMd];
__device__ float g_vt[Mrows * DIMd];
__device__ float g_wq[DIMd * DIMd];          // tf32 perm-k copies of weights
__device__ float g_wk[DIMd * DIMd];
__device__ float g_wv[DIMd * DIMd];
__device__ float g_wo[DIMd * DIMd];

__device__ __forceinline__ uint32_t tf32r(float x) {
    uint32_t y;
    asm("cvt.rna.tf32.f32 %0, %1;" : "=r"(y) : "f"(x));
    return y;
}

__device__ __forceinline__ void mma8(float* d, const uint32_t* a, const uint32_t* b) {
    asm volatile(
        "mma.sync.aligned.m16n8k8.row.col.f32.tf32.tf32.f32 "
        "{%0,%1,%2,%3}, {%4,%5,%6,%7}, {%8,%9}, {%0,%1,%2,%3};\n"
        : "+f"(d[0]), "+f"(d[1]), "+f"(d[2]), "+f"(d[3])
        : "r"(a[0]), "r"(a[1]), "r"(a[2]), "r"(a[3]), "r"(b[0]), "r"(b[1]));
}

__device__ __forceinline__ void cp16(uint32_t daddr, const void* src) {
    asm volatile("cp.async.cg.shared.global [%0], [%1], 16;\n"
                 :: "r"(daddr), "l"(src));
}
__device__ __forceinline__ void cp_commit() {
    asm volatile("cp.async.commit_group;\n");
}
template <int N>
__device__ __forceinline__ void cp_wait() {
    asm volatile("cp.async.wait_group %0;\n" :: "n"(N));
}

// ---------------------------------------------------------------------------
// Fused tf32 (RNA) conversion + k-group permute (one launch).
// ---------------------------------------------------------------------------
__global__ __launch_bounds__(256) void cvt_all(
    const float4* q, const float4* k, const float4* v,
    const float4* wq, const float4* wk, const float4* wv, const float4* wo,
    float4* qt, float4* kt, float4* vt,
    float4* dwq, float4* dwk, float4* dwv, float4* dwo)
{
    const int z = blockIdx.z;
    const int n8 = (z < 3) ? (Mrows * DIMd / 8) : (DIMd * DIMd / 8);
    const int i = blockIdx.x * 256 + threadIdx.x;
    if (i >= n8) return;
    const float4* s;
    float4* d;
    switch (z) {
        case 0: s = q;  d = qt;  break;
        case 1: s = k;  d = kt;  break;
        case 2: s = v;  d = vt;  break;
        case 3: s = wq; d = dwq; break;
        case 4: s = wk; d = dwk; break;
        case 5: s = wv; d = dwv; break;
        default: s = wo; d = dwo; break;
    }
    const float4 a = s[2 * i];       // logical k 0..3
    const float4 b = s[2 * i + 1];   // logical k 4..7
    float4 o0, o1;
    o0.x = __uint_as_float(tf32r(a.x)); o0.y = __uint_as_float(tf32r(b.x));
    o0.z = __uint_as_float(tf32r(a.y)); o0.w = __uint_as_float(tf32r(b.y));
    o1.x = __uint_as_float(tf32r(a.z)); o1.y = __uint_as_float(tf32r(b.z));
    o1.z = __uint_as_float(tf32r(a.w)); o1.w = __uint_as_float(tf32r(b.w));
    d[2 * i]     = o0;
    d[2 * i + 1] = o1;
}

// ---------------------------------------------------------------------------
// Projection GEMM (R9 proven): 128x128x32 tiles, 2-stage cp.async double
// buffer {issue(kt+1); wait<1>; sync; mma; sync}, 81.9KB smem,
// __launch_bounds__(256,2) -> 2 CTAs/SM, perm-k LDS.64 fragments.
// ---------------------------------------------------------------------------
constexpr int SKA = 40;                        // smem k-stride words
constexpr int PROJ_SMEM = 4 * 128 * SKA * 4;   // 81920 B

template <bool SPLIT_IN, bool SPLIT_OUT, bool ROUND>
__device__ __forceinline__ void proj_body(
    const float* __restrict__ A, const float* __restrict__ W,
    const float* __restrict__ bias, float* __restrict__ C, float scale,
    float* smf)
{
    const int m0 = blockIdx.y * 128, n0 = blockIdx.x * 128;
    const int tid = threadIdx.x;
    const int w = tid >> 5, lane = tid & 31;
    const int gid = lane >> 2, tig = lane & 3;
    const int mbase = (w & 1) * 64;
    const int nbase = (w >> 1) * 32;

    const uint32_t* Asb[2] = {(const uint32_t*)smf,
                              (const uint32_t*)smf + 128 * SKA};
    const uint32_t* Wsb[2] = {(const uint32_t*)smf + 2 * 128 * SKA,
                              (const uint32_t*)smf + 3 * 128 * SKA};
    const uint32_t su = (uint32_t)__cvta_generic_to_shared(smf);
    const uint32_t asu[2] = {su, su + 128 * SKA * 4};
    const uint32_t wsu[2] = {su + 2 * 128 * SKA * 4, su + 3 * 128 * SKA * 4};

    auto load_tiles = [&](int kt, int buf) {
        const int k0 = kt * 32;
#pragma unroll
        for (int t = 0; t < 4; t++) {
            const int idx = tid + t * 256;
            const int r = idx >> 3, c = (idx & 7) << 2;
            const float* ap;
            if (SPLIT_IN) {
                const int gm = m0 + r, gk = k0 + c;
                const int b = gm >> 11, tok = gm & (Nn - 1);
                const int h = gk >> 6, cc = gk & 63;
                ap = A + ((size_t)((b * Hh + h) * Nn + tok)) * HDc + cc;
            } else {
                ap = A + (size_t)(m0 + r) * DIMd + k0 + c;
            }
            cp16(asu[buf] + (r * SKA + c) * 4, ap);
            cp16(wsu[buf] + (r * SKA + c) * 4,
                 W + (size_t)(n0 + r) * DIMd + k0 + c);
        }
        cp_commit();
    };

    float c[4][4][4];
#pragma unroll
    for (int mi = 0; mi < 4; mi++)
#pragma unroll
        for (int ni = 0; ni < 4; ni++)
#pragma unroll
            for (int u = 0; u < 4; u++) c[mi][ni][u] = 0.f;

    load_tiles(0, 0);
    constexpr int ITERS = DIMd / 32;  // 32
    for (int kt = 0; kt < ITERS; kt++) {
        const int cur = kt & 1;
        if (kt + 1 < ITERS) { load_tiles(kt + 1, cur ^ 1); cp_wait<1>(); }
        else                { cp_wait<0>(); }
        __syncthreads();

        const uint32_t* Ab = Asb[cur];
        const uint32_t* Wb = Wsb[cur];
#pragma unroll
        for (int kk = 0; kk < 32; kk += 8) {
            uint32_t af[4][4];
#pragma unroll
            for (int mi = 0; mi < 4; mi++) {
                const int row = mbase + mi * 16 + gid;
                const uint2 a0 = *reinterpret_cast<const uint2*>(
                    Ab + row * SKA + kk + 2 * tig);
                const uint2 a1 = *reinterpret_cast<const uint2*>(
                    Ab + (row + 8) * SKA + kk + 2 * tig);
                af[mi][0] = a0.x; af[mi][1] = a1.x;
                af[mi][2] = a0.y; af[mi][3] = a1.y;
            }
            uint32_t bf[4][2];
#pragma unroll
            for (int ni = 0; ni < 4; ni++) {
                const uint2 b = *reinterpret_cast<const uint2*>(
                    Wb + (nbase + ni * 8 + gid) * SKA + kk + 2 * tig);
                bf[ni][0] = b.x;
                bf[ni][1] = b.y;
            }
#pragma unroll
            for (int mi = 0; mi < 4; mi++)
#pragma unroll
                for (int ni = 0; ni < 4; ni++)
                    mma8(c[mi][ni], af[mi], bf[ni]);
        }
        __syncthreads();
    }

    // Epilogue. Logical cols 2tig, 2tig+1 -> permuted head positions p0, p0+2.
    const int p0 = (tig < 2) ? 4 * tig : 4 * tig - 7;
#pragma unroll
    for (int mi = 0; mi < 4; mi++) {
#pragma unroll
        for (int ni = 0; ni < 4; ni++) {
            const int nlog = n0 + nbase + ni * 8 + 2 * tig;
            const float bx = bias[nlog], by = bias[nlog + 1];
#pragma unroll
            for (int hr = 0; hr < 2; hr++) {
                const int m = m0 + mbase + mi * 16 + gid + hr * 8;
                float ox = (c[mi][ni][hr * 2 + 0] + bx) * scale;
                float oy = (c[mi][ni][hr * 2 + 1] + by) * scale;
                if (ROUND) {
                    ox = __uint_as_float(tf32r(ox));
                    oy = __uint_as_float(tf32r(oy));
                }
                if (SPLIT_OUT) {
                    const int b = m >> 11, tok = m & (Nn - 1);
                    const int np0 = n0 + nbase + ni * 8 + p0;
                    const int h = np0 >> 6;
                    float* dst = C + ((size_t)((b * Hh + h) * Nn + tok)) * HDc;
                    dst[np0 & 63]       = ox;
                    dst[(np0 + 2) & 63] = oy;
                } else {
                    float2 o; o.x = ox; o.y = oy;
                    *reinterpret_cast<float2*>(C + (size_t)m * DIMd + nlog) = o;
                }
            }
        }
    }
}

__global__ __launch_bounds__(256, 2) void qkv_proj(
    const float* aq, const float* ak, const float* av,
    const float* wq, const float* wk, const float* wv,
    const float* bq, const float* bk, const float* bv,
    float* cq, float* ck, float* cv)
{
    extern __shared__ float smf[];
    const int z = blockIdx.z;
    const float* A = (z == 0) ? aq : (z == 1) ? ak : av;
    const float* W = (z == 0) ? wq : (z == 1) ? wk : wv;
    const float* b = (z == 0) ? bq : (z == 1) ? bk : bv;
    float*       C = (z == 0) ? cq : (z == 1) ? ck : cv;
    const float scale = (z == 0) ? ATTN_SCALE : 1.0f;
    proj_body<false, true, true>(A, W, b, C, scale, smf);
}

__global__ __launch_bounds__(256, 2) void o_proj(
    const float* A, const float* W, const float* b, float* C)
{
    extern __shared__ float smf[];
    proj_body<true, false, false>(A, W, b, C, 1.0f, smf);
}

// ---------------------------------------------------------------------------
// Causal flash attention: 64 q-rows/CTA, 128 threads (4 warps, 16x64 strips),
// register softmax, R9 pipeline {issue; wait<1>; sync; compute; sync},
// heavy-first. K tile token rows stored PERMUTED => S cols are perm-token
// order => PV A-frag is a register rename of softmax output (NO P smem).
// Smem 72KB -> 3 CTAs/SM.
// ---------------------------------------------------------------------------
constexpr int AST = 72;  // smem row stride (words)
constexpr int ATT_SMEM = 4 * 64 * AST * 4;  // 2xK, 2xV = 73728 B

__global__ __launch_bounds__(128, 3) void attn2(
    const float* __restrict__ Qg, const float* __restrict__ Kg,
    const float* __restrict__ Vg, float* __restrict__ Og)
{
    extern __shared__ float smf[];
    const uint32_t su = (uint32_t)__cvta_generic_to_shared(smf);
    const uint32_t ksu[2] = {su, su + 64 * AST * 4};
    const uint32_t vsu[2] = {su + 2 * 64 * AST * 4, su + 3 * 64 * AST * 4};
    const uint32_t* Ksb[2] = {(const uint32_t*)smf,
                              (const uint32_t*)smf + 64 * AST};
    const uint32_t* Vsb[2] = {(const uint32_t*)smf + 2 * 64 * AST,
                              (const uint32_t*)smf + 3 * 64 * AST};

    const int bh = blockIdx.y;
    const int qt = (gridDim.x - 1) - blockIdx.x;   // heavy-first
    const int q0 = qt * 64;
    const size_t base = (size_t)bh * Nn * HDc;

    const int tid = threadIdx.x;
    const int w = tid >> 5, lane = tid & 31;
    const int gid = lane >> 2, tig = lane & 3;
    const int mrow = w * 16;

    auto issueKV = [&](int t_kt, int buf) {
        const float* Kb = Kg + base + (size_t)(t_kt * 64) * HDc;
        const float* Vb = Vg + base + (size_t)(t_kt * 64) * HDc;
#pragma unroll
        for (int t = 0; t < 8; t++) {
            const int idx = tid + t * 128;
            const int r = idx >> 4, cc = (idx & 15) << 2;
            // K rows stored at permuted positions within each 8-token group:
            // token 8g+t -> row 8g + (t<4 ? 2t : 2(t-4)+1)
            const int pr = (r & ~7) | ((r & 3) << 1) | ((r >> 2) & 1);
            cp16(ksu[buf] + (pr * AST + cc) * 4, Kb + r * HDc + cc);
            // V rows stay in logical token order
            cp16(vsu[buf] + (r * AST + cc) * 4, Vb + r * HDc + cc);
        }
        cp_commit();
    };

    // Q fragments from perm-k qh: 64-bit pairs at 2tig
    uint32_t qf[8][4];
    {
        const uint32_t* Qu = (const uint32_t*)(Qg + base) +
                             (size_t)(q0 + mrow + gid) * HDc;
#pragma unroll
        for (int s = 0; s < 8; s++) {
            const uint2 u0 = *reinterpret_cast<const uint2*>(Qu + s * 8 + 2 * tig);
            const uint2 u1 = *reinterpret_cast<const uint2*>(Qu + 8 * HDc + s * 8 + 2 * tig);
            qf[s][0] = u0.x; qf[s][1] = u1.x;
            qf[s][2] = u0.y; qf[s][3] = u1.y;
        }
    }

    float o[8][4];
#pragma unroll
    for (int ni = 0; ni < 8; ni++)
#pragma unroll
        for (int u = 0; u < 4; u++) o[ni][u] = 0.f;
    float m0r = -1e30f, m1r = -1e30f, l0 = 0.f, l1 = 0.f;

    issueKV(0, 0);

    for (int kt = 0; kt <= qt; kt++) {
        const int cur = kt & 1;
        if (kt < qt) { issueKV(kt + 1, cur ^ 1); cp_wait<1>(); }
        else         { cp_wait<0>(); }
        __syncthreads();

        // ---- S = Q K^T (16x64 per warp); LDS.64 K frags.
        //      S col 2tig = logical token ni*8+tig; col 2tig+1 = token +4. ----
        float s4[8][4];
#pragma unroll
        for (int ni = 0; ni < 8; ni++)
#pragma unroll
            for (int u = 0; u < 4; u++) s4[ni][u] = 0.f;

        const uint32_t* Kb = Ksb[cur];
#pragma unroll
        for (int s = 0; s < 8; s++) {
            const int kk = s * 8;
            uint32_t bf[8][2];
#pragma unroll
            for (int ni = 0; ni < 8; ni++) {
                const uint2 b = *reinterpret_cast<const uint2*>(
                    Kb + (ni * 8 + gid) * AST + kk + 2 * tig);
                bf[ni][0] = b.x;
                bf[ni][1] = b.y;
            }
#pragma unroll
            for (int ni = 0; ni < 8; ni++)
                mma8(s4[ni], qf[s], bf[ni]);
        }

        // ---- causal mask (diagonal tile only; perm-token columns) ----
        if (kt == qt) {
            const int r0 = q0 + mrow + gid, r1 = r0 + 8;
            const int k0 = kt * 64;
#pragma unroll
            for (int ni = 0; ni < 8; ni++) {
                const int c0 = k0 + ni * 8 + tig;   // token for [0],[2]
                const int c1 = c0 + 4;              // token for [1],[3]
                if (c0 > r0) s4[ni][0] = -1e30f;
                if (c1 > r0) s4[ni][1] = -1e30f;
                if (c0 > r1) s4[ni][2] = -1e30f;
                if (c1 > r1) s4[ni][3] = -1e30f;
            }
        }

        // ---- register softmax (rows warp-local; quad reduction) ----
        float mx0 = -1e30f, mx1 = -1e30f;
#pragma unroll
        for (int ni = 0; ni < 8; ni++) {
            mx0 = fmaxf(mx0, fmaxf(s4[ni][0], s4[ni][1]));
            mx1 = fmaxf(mx1, fmaxf(s4[ni][2], s4[ni][3]));
        }
        mx0 = fmaxf(mx0, __shfl_xor_sync(0xffffffffu, mx0, 1));
        mx0 = fmaxf(mx0, __shfl_xor_sync(0xffffffffu, mx0, 2));
        mx1 = fmaxf(mx1, __shfl_xor_sync(0xffffffffu, mx1, 1));
        mx1 = fmaxf(mx1, __shfl_xor_sync(0xffffffffu, mx1, 2));
        const float mn0 = fmaxf(m0r, mx0);
        const float mn1 = fmaxf(m1r, mx1);
        const float f0 = __expf(m0r - mn0);
        const float f1 = __expf(m1r - mn1);
        m0r = mn0; m1r = mn1;

        // P kept in registers (overwrite s4 with tf32-rounded probabilities)
        float sum0 = 0.f, sum1 = 0.f;
#pragma unroll
        for (int ni = 0; ni < 8; ni++) {
            const float e0 = __expf(s4[ni][0] - mn0);
            const float e1 = __expf(s4[ni][1] - mn0);
            const float e2 = __expf(s4[ni][2] - mn1);
            const float e3 = __expf(s4[ni][3] - mn1);
            sum0 += e0 + e1;
            sum1 += e2 + e3;
            s4[ni][0] = __uint_as_float(tf32r(e0));
            s4[ni][1] = __uint_as_float(tf32r(e1));
            s4[ni][2] = __uint_as_float(tf32r(e2));
            s4[ni][3] = __uint_as_float(tf32r(e3));
        }
        sum0 += __shfl_xor_sync(0xffffffffu, sum0, 1);
        sum0 += __shfl_xor_sync(0xffffffffu, sum0, 2);
        sum1 += __shfl_xor_sync(0xffffffffu, sum1, 1);
        sum1 += __shfl_xor_sync(0xffffffffu, sum1, 2);
        l0 = l0 * f0 + sum0;
        l1 = l1 * f1 + sum1;

#pragma unroll
        for (int ni = 0; ni < 8; ni++) {
            o[ni][0] *= f0; o[ni][1] *= f0;
            o[ni][2] *= f1; o[ni][3] *= f1;
        }

        // ---- O += P * V; A-frag = register rename of s4 (tokens tig, tig+4
        //      at a0/a2 — exactly the mma's k layout); V rows logical ----
        const uint32_t* Vb = Vsb[cur];
#pragma unroll
        for (int s = 0; s < 8; s++) {
            const int kk = s * 8;
            uint32_t af[4];
            af[0] = __float_as_uint(s4[s][0]);  // k=tig,   row gid
            af[1] = __float_as_uint(s4[s][2]);  // k=tig,   row gid+8
            af[2] = __float_as_uint(s4[s][1]);  // k=tig+4, row gid
            af[3] = __float_as_uint(s4[s][3]);  // k=tig+4, row gid+8
            uint32_t bf[8][2];
#pragma unroll
            for (int ni = 0; ni < 8; ni++) {
                const uint32_t* q = Vb + (kk + tig) * AST + ni * 8 + gid;
                bf[ni][0] = q[0];
                bf[ni][1] = q[4 * AST];
            }
#pragma unroll
            for (int ni = 0; ni < 8; ni++)
                mma8(o[ni], af, bf[ni]);
        }
        __syncthreads();
    }

    // ---- finalize (cols = perm head positions, matching o_proj input) ----
    {
        const float inv0 = 1.f / l0;
        const float inv1 = 1.f / l1;
        const int r0 = q0 + mrow + gid;
        uint32_t* Ou = (uint32_t*)(Og + base);
#pragma unroll
        for (int ni = 0; ni < 8; ni++) {
            const int cc = ni * 8 + 2 * tig;
            uint2 oa, ob;
            oa.x = tf32r(o[ni][0] * inv0);
            oa.y = tf32r(o[ni][1] * inv0);
            ob.x = tf32r(o[ni][2] * inv1);
            ob.y = tf32r(o[ni][3] * inv1);
            *reinterpret_cast<uint2*>(Ou + (size_t)r0 * HDc + cc) = oa;
            *reinterpret_cast<uint2*>(Ou + (size_t)(r0 + 8) * HDc + cc) = ob;
        }
    }
}

// ---------------------------------------------------------------------------
extern "C" void kernel_launch(void* const* d_in, const int* in_sizes, int n_in,
                              void* d_out, int out_size)
{
    const float* q  = (const float*)d_in[0];
    const float* k  = (const float*)d_in[1];
    const float* v  = (const float*)d_in[2];
    // d_in[3] = mask (tril; causality applied analytically)
    const float* Wq = (const float*)d_in[4];
    const float* bq = (const float*)d_in[5];
    const float* Wk = (const float*)d_in[6];
    const float* bk = (const float*)d_in[7];
    const float* Wv = (const float*)d_in[8];
    const float* bv = (const float*)d_in[9];
    const float* Wo = (const float*)d_in[10];
    const float* bo = (const float*)d_in[11];
    float* out = (float*)d_out;

    float *qh, *kh, *vh, *ao, *qt, *kt, *vt, *wq, *wk, *wv, *wo;
    cudaGetSymbolAddress((void**)&qh, g_qh);
    cudaGetSymbolAddress((void**)&kh, g_kh);
    cudaGetSymbolAddress((void**)&vh, g_vh);
    cudaGetSymbolAddress((void**)&ao, g_ao);
    cudaGetSymbolAddress((void**)&qt, g_qt);
    cudaGetSymbolAddress((void**)&kt, g_kt);
    cudaGetSymbolAddress((void**)&vt, g_vt);
    cudaGetSymbolAddress((void**)&wq, g_wq);
    cudaGetSymbolAddress((void**)&wk, g_wk);
    cudaGetSymbolAddress((void**)&wv, g_wv);
    cudaGetSymbolAddress((void**)&wo, g_wo);

    static int cfg = 0;
    if (!cfg) {
        cudaFuncSetAttribute(qkv_proj,
            cudaFuncAttributeMaxDynamicSharedMemorySize, PROJ_SMEM);
        cudaFuncSetAttribute(o_proj,
            cudaFuncAttributeMaxDynamicSharedMemorySize, PROJ_SMEM);
        cudaFuncSetAttribute(attn2,
            cudaFuncAttributeMaxDynamicSharedMemorySize, ATT_SMEM);
        cfg = 1;
    }

    // tf32 + perm-k conversion, one launch
    const int blocks_x = (Mrows * DIMd / 8 + 255) / 256;  // 2048
    cvt_all<<<dim3(blocks_x, 1, 7), 256>>>(
        (const float4*)q, (const float4*)k, (const float4*)v,
        (const float4*)Wq, (const float4*)Wk, (const float4*)Wv, (const float4*)Wo,
        (float4*)qt, (float4*)kt, (float4*)vt,
        (float4*)wq, (float4*)wk, (float4*)wv, (float4*)wo);

    // Fused QKV projections (Q pre-scaled by ATTN_SCALE in epilogue)
    qkv_proj<<<dim3(DIMd / 128, Mrows / 128, 3), 256, PROJ_SMEM>>>(
        qt, kt, vt, wq, wk, wv, bq, bk, bv, qh, kh, vh);

    // Attention: 64 q-rows per CTA, heavy tiles first
    attn2<<<dim3(Nn / 64, Bb * Hh), 128, ATT_SMEM>>>(qh, kh, vh, ao);

    // Output projection
    o_proj<<<dim3(DIMd / 128, Mrows / 128), 256, PROJ_SMEM>>>(ao, wo, bo, out);
}

// round 14
// speedup vs baseline: 1.1005x; 1.0044x over previous
#include <cuda_runtime.h>
#include <math.h>
#include <stdint.h>

constexpr int Bb   = 2;
constexpr int Hh   = 16;
constexpr int Nn   = 2048;
constexpr int HDc  = 64;
constexpr int DIMd = 1024;
constexpr int Mrows = Bb * Nn;       // 4096
constexpr float ATTN_SCALE = 0.125f;
constexpr float LOG2E = 1.44269504088896340736f;

// k-group permutation: storage position 2t holds logical k t, 2t+1 holds t+4.
// In attention, K tile token ROWS are stored permuted => S cols land in
// perm-token order => PV A-frag is a register rename of softmax output.
// Softmax runs in the exp2 domain (log2e folded into the Q projection scale).

// Scratch buffers
__device__ float g_qh[Bb * Hh * Nn * HDc];   // Q heads (tf32, perm, pre-scaled by s*log2e)
__device__ float g_kh[Bb * Hh * Nn * HDc];   // K heads (tf32, perm head dim)
__device__ float g_vh[Bb * Hh * Nn * HDc];   // V heads (tf32, perm head dim)
__device__ float g_ao[Bb * Hh * Nn * HDc];   // attn out (tf32, perm head dim)
__device__ float g_qt[Mrows * DIMd];         // tf32 perm-k copies of inputs
__device__ float g_kt[Mrows * DIMd];
__device__ float g_vt[Mrows * DIMd];
__device__ float g_wq[DIMd * DIMd];          // tf32 perm-k copies of weights
__device__ float g_wk[DIMd * DIMd];
__device__ float g_wv[DIMd * DIMd];
__device__ float g_wo[DIMd * DIMd];

__device__ __forceinline__ uint32_t tf32r(float x) {
    uint32_t y;
    asm("cvt.rna.tf32.f32 %0, %1;" : "=r"(y) : "f"(x));
    return y;
}

__device__ __forceinline__ float ex2(float x) {
    float y;
    asm("ex2.approx.f32 %0, %1;" : "=f"(y) : "f"(x));
    return y;
}

__device__ __forceinline__ void mma8(float* d, const uint32_t* a, const uint32_t* b) {
    asm volatile(
        "mma.sync.aligned.m16n8k8.row.col.f32.tf32.tf32.f32 "
        "{%0,%1,%2,%3}, {%4,%5,%6,%7}, {%8,%9}, {%0,%1,%2,%3};\n"
        : "+f"(d[0]), "+f"(d[1]), "+f"(d[2]), "+f"(d[3])
        : "r"(a[0]), "r"(a[1]), "r"(a[2]), "r"(a[3]), "r"(b[0]), "r"(b[1]));
}

__device__ __forceinline__ void cp16(uint32_t daddr, const void* src) {
    asm volatile("cp.async.cg.shared.global [%0], [%1], 16;\n"
                 :: "r"(daddr), "l"(src));
}
__device__ __forceinline__ void cp_commit() {
    asm volatile("cp.async.commit_group;\n");
}
template <int N>
__device__ __forceinline__ void cp_wait() {
    asm volatile("cp.async.wait_group %0;\n" :: "n"(N));
}

// ---------------------------------------------------------------------------
// Fused tf32 (RNA) conversion + k-group permute (one launch).
// ---------------------------------------------------------------------------
__global__ __launch_bounds__(256) void cvt_all(
    const float4* q, const float4* k, const float4* v,
    const float4* wq, const float4* wk, const float4* wv, const float4* wo,
    float4* qt, float4* kt, float4* vt,
    float4* dwq, float4* dwk, float4* dwv, float4* dwo)
{
    const int z = blockIdx.z;
    const int n8 = (z < 3) ? (Mrows * DIMd / 8) : (DIMd * DIMd / 8);
    const int i = blockIdx.x * 256 + threadIdx.x;
    if (i >= n8) return;
    const float4* s;
    float4* d;
    switch (z) {
        case 0: s = q;  d = qt;  break;
        case 1: s = k;  d = kt;  break;
        case 2: s = v;  d = vt;  break;
        case 3: s = wq; d = dwq; break;
        case 4: s = wk; d = dwk; break;
        case 5: s = wv; d = dwv; break;
        default: s = wo; d = dwo; break;
    }
    const float4 a = s[2 * i];       // logical k 0..3
    const float4 b = s[2 * i + 1];   // logical k 4..7
    float4 o0, o1;
    o0.x = __uint_as_float(tf32r(a.x)); o0.y = __uint_as_float(tf32r(b.x));
    o0.z = __uint_as_float(tf32r(a.y)); o0.w = __uint_as_float(tf32r(b.y));
    o1.x = __uint_as_float(tf32r(a.z)); o1.y = __uint_as_float(tf32r(b.z));
    o1.z = __uint_as_float(tf32r(a.w)); o1.w = __uint_as_float(tf32r(b.w));
    d[2 * i]     = o0;
    d[2 * i + 1] = o1;
}

// ---------------------------------------------------------------------------
// Projection GEMM (R9/R13 proven): 128x128x32 tiles, 2-stage cp.async double
// buffer {issue(kt+1); wait<1>; sync; mma; sync}, 81.9KB smem,
// __launch_bounds__(256,2) -> 2 CTAs/SM, perm-k LDS.64 fragments.
// ---------------------------------------------------------------------------
constexpr int SKA = 40;                        // smem k-stride words
constexpr int PROJ_SMEM = 4 * 128 * SKA * 4;   // 81920 B

template <bool SPLIT_IN, bool SPLIT_OUT, bool ROUND>
__device__ __forceinline__ void proj_body(
    const float* __restrict__ A, const float* __restrict__ W,
    const float* __restrict__ bias, float* __restrict__ C, float scale,
    float* smf)
{
    const int m0 = blockIdx.y * 128, n0 = blockIdx.x * 128;
    const int tid = threadIdx.x;
    const int w = tid >> 5, lane = tid & 31;
    const int gid = lane >> 2, tig = lane & 3;
    const int mbase = (w & 1) * 64;
    const int nbase = (w >> 1) * 32;

    const uint32_t* Asb[2] = {(const uint32_t*)smf,
                              (const uint32_t*)smf + 128 * SKA};
    const uint32_t* Wsb[2] = {(const uint32_t*)smf + 2 * 128 * SKA,
                              (const uint32_t*)smf + 3 * 128 * SKA};
    const uint32_t su = (uint32_t)__cvta_generic_to_shared(smf);
    const uint32_t asu[2] = {su, su + 128 * SKA * 4};
    const uint32_t wsu[2] = {su + 2 * 128 * SKA * 4, su + 3 * 128 * SKA * 4};

    auto load_tiles = [&](int kt, int buf) {
        const int k0 = kt * 32;
#pragma unroll
        for (int t = 0; t < 4; t++) {
            const int idx = tid + t * 256;
            const int r = idx >> 3, c = (idx & 7) << 2;
            const float* ap;
            if (SPLIT_IN) {
                const int gm = m0 + r, gk = k0 + c;
                const int b = gm >> 11, tok = gm & (Nn - 1);
                const int h = gk >> 6, cc = gk & 63;
                ap = A + ((size_t)((b * Hh + h) * Nn + tok)) * HDc + cc;
            } else {
                ap = A + (size_t)(m0 + r) * DIMd + k0 + c;
            }
            cp16(asu[buf] + (r * SKA + c) * 4, ap);
            cp16(wsu[buf] + (r * SKA + c) * 4,
                 W + (size_t)(n0 + r) * DIMd + k0 + c);
        }
        cp_commit();
    };

    float c[4][4][4];
#pragma unroll
    for (int mi = 0; mi < 4; mi++)
#pragma unroll
        for (int ni = 0; ni < 4; ni++)
#pragma unroll
            for (int u = 0; u < 4; u++) c[mi][ni][u] = 0.f;

    load_tiles(0, 0);
    constexpr int ITERS = DIMd / 32;  // 32
    for (int kt = 0; kt < ITERS; kt++) {
        const int cur = kt & 1;
        if (kt + 1 < ITERS) { load_tiles(kt + 1, cur ^ 1); cp_wait<1>(); }
        else                { cp_wait<0>(); }
        __syncthreads();

        const uint32_t* Ab = Asb[cur];
        const uint32_t* Wb = Wsb[cur];
#pragma unroll
        for (int kk = 0; kk < 32; kk += 8) {
            uint32_t af[4][4];
#pragma unroll
            for (int mi = 0; mi < 4; mi++) {
                const int row = mbase + mi * 16 + gid;
                const uint2 a0 = *reinterpret_cast<const uint2*>(
                    Ab + row * SKA + kk + 2 * tig);
                const uint2 a1 = *reinterpret_cast<const uint2*>(
                    Ab + (row + 8) * SKA + kk + 2 * tig);
                af[mi][0] = a0.x; af[mi][1] = a1.x;
                af[mi][2] = a0.y; af[mi][3] = a1.y;
            }
            uint32_t bf[4][2];
#pragma unroll
            for (int ni = 0; ni < 4; ni++) {
                const uint2 b = *reinterpret_cast<const uint2*>(
                    Wb + (nbase + ni * 8 + gid) * SKA + kk + 2 * tig);
                bf[ni][0] = b.x;
                bf[ni][1] = b.y;
            }
#pragma unroll
            for (int mi = 0; mi < 4; mi++)
#pragma unroll
                for (int ni = 0; ni < 4; ni++)
                    mma8(c[mi][ni], af[mi], bf[ni]);
        }
        __syncthreads();
    }

    // Epilogue. Logical cols 2tig, 2tig+1 -> permuted head positions p0, p0+2.
    const int p0 = (tig < 2) ? 4 * tig : 4 * tig - 7;
#pragma unroll
    for (int mi = 0; mi < 4; mi++) {
#pragma unroll
        for (int ni = 0; ni < 4; ni++) {
            const int nlog = n0 + nbase + ni * 8 + 2 * tig;
            const float bx = bias[nlog], by = bias[nlog + 1];
#pragma unroll
            for (int hr = 0; hr < 2; hr++) {
                const int m = m0 + mbase + mi * 16 + gid + hr * 8;
                float ox = (c[mi][ni][hr * 2 + 0] + bx) * scale;
                float oy = (c[mi][ni][hr * 2 + 1] + by) * scale;
                if (ROUND) {
                    ox = __uint_as_float(tf32r(ox));
                    oy = __uint_as_float(tf32r(oy));
                }
                if (SPLIT_OUT) {
                    const int b = m >> 11, tok = m & (Nn - 1);
                    const int np0 = n0 + nbase + ni * 8 + p0;
                    const int h = np0 >> 6;
                    float* dst = C + ((size_t)((b * Hh + h) * Nn + tok)) * HDc;
                    dst[np0 & 63]       = ox;
                    dst[(np0 + 2) & 63] = oy;
                } else {
                    float2 o; o.x = ox; o.y = oy;
                    *reinterpret_cast<float2*>(C + (size_t)m * DIMd + nlog) = o;
                }
            }
        }
    }
}

__global__ __launch_bounds__(256, 2) void qkv_proj(
    const float* aq, const float* ak, const float* av,
    const float* wq, const float* wk, const float* wv,
    const float* bq, const float* bk, const float* bv,
    float* cq, float* ck, float* cv)
{
    extern __shared__ float smf[];
    const int z = blockIdx.z;
    const float* A = (z == 0) ? aq : (z == 1) ? ak : av;
    const float* W = (z == 0) ? wq : (z == 1) ? wk : wv;
    const float* b = (z == 0) ? bq : (z == 1) ? bk : bv;
    float*       C = (z == 0) ? cq : (z == 1) ? ck : cv;
    // Q gets attn scale AND log2e folded in (softmax runs in exp2 domain)
    const float scale = (z == 0) ? ATTN_SCALE * LOG2E : 1.0f;
    proj_body<false, true, true>(A, W, b, C, scale, smf);
}

__global__ __launch_bounds__(256, 2) void o_proj(
    const float* A, const float* W, const float* b, float* C)
{
    extern __shared__ float smf[];
    proj_body<true, false, false>(A, W, b, C, 1.0f, smf);
}

// ---------------------------------------------------------------------------
// Causal flash attention (R13): 64 q-rows/CTA, 128 threads (4 warps, 16x64
// strips), register softmax in exp2 domain, heavy-first, K rows perm-stored,
// PV A-frag = register rename, no P smem. 73.7KB smem -> 3 CTAs/SM.
// ---------------------------------------------------------------------------
constexpr int AST = 72;  // smem row stride (words)
constexpr int ATT_SMEM = 4 * 64 * AST * 4;  // 2xK, 2xV = 73728 B

__global__ __launch_bounds__(128, 3) void attn2(
    const float* __restrict__ Qg, const float* __restrict__ Kg,
    const float* __restrict__ Vg, float* __restrict__ Og)
{
    extern __shared__ float smf[];
    const uint32_t su = (uint32_t)__cvta_generic_to_shared(smf);
    const uint32_t ksu[2] = {su, su + 64 * AST * 4};
    const uint32_t vsu[2] = {su + 2 * 64 * AST * 4, su + 3 * 64 * AST * 4};
    const uint32_t* Ksb[2] = {(const uint32_t*)smf,
                              (const uint32_t*)smf + 64 * AST};
    const uint32_t* Vsb[2] = {(const uint32_t*)smf + 2 * 64 * AST,
                              (const uint32_t*)smf + 3 * 64 * AST};

    const int bh = blockIdx.y;
    const int qt = (gridDim.x - 1) - blockIdx.x;   // heavy-first
    const int q0 = qt * 64;
    const size_t base = (size_t)bh * Nn * HDc;

    const int tid = threadIdx.x;
    const int w = tid >> 5, lane = tid & 31;
    const int gid = lane >> 2, tig = lane & 3;
    const int mrow = w * 16;

    auto issueKV = [&](int t_kt, int buf) {
        const float* Kb = Kg + base + (size_t)(t_kt * 64) * HDc;
        const float* Vb = Vg + base + (size_t)(t_kt * 64) * HDc;
#pragma unroll
        for (int t = 0; t < 8; t++) {
            const int idx = tid + t * 128;
            const int r = idx >> 4, cc = (idx & 15) << 2;
            // K rows stored at permuted positions within each 8-token group
            const int pr = (r & ~7) | ((r & 3) << 1) | ((r >> 2) & 1);
            cp16(ksu[buf] + (pr * AST + cc) * 4, Kb + r * HDc + cc);
            cp16(vsu[buf] + (r * AST + cc) * 4, Vb + r * HDc + cc);
        }
        cp_commit();
    };

    // Q fragments from perm-k qh: 64-bit pairs at 2tig
    uint32_t qf[8][4];
    {
        const uint32_t* Qu = (const uint32_t*)(Qg + base) +
                             (size_t)(q0 + mrow + gid) * HDc;
#pragma unroll
        for (int s = 0; s < 8; s++) {
            const uint2 u0 = *reinterpret_cast<const uint2*>(Qu + s * 8 + 2 * tig);
            const uint2 u1 = *reinterpret_cast<const uint2*>(Qu + 8 * HDc + s * 8 + 2 * tig);
            qf[s][0] = u0.x; qf[s][1] = u1.x;
            qf[s][2] = u0.y; qf[s][3] = u1.y;
        }
    }

    float o[8][4];
#pragma unroll
    for (int ni = 0; ni < 8; ni++)
#pragma unroll
        for (int u = 0; u < 4; u++) o[ni][u] = 0.f;
    float m0r = -1e30f, m1r = -1e30f, l0 = 0.f, l1 = 0.f;

    issueKV(0, 0);

    for (int kt = 0; kt <= qt; kt++) {
        const int cur = kt & 1;
        if (kt < qt) { issueKV(kt + 1, cur ^ 1); cp_wait<1>(); }
        else         { cp_wait<0>(); }
        __syncthreads();

        // ---- S = Q K^T (16x64 per warp); LDS.64 K frags; S in log2 units ----
        float s4[8][4];
#pragma unroll
        for (int ni = 0; ni < 8; ni++)
#pragma unroll
            for (int u = 0; u < 4; u++) s4[ni][u] = 0.f;

        const uint32_t* Kb = Ksb[cur];
#pragma unroll
        for (int s = 0; s < 8; s++) {
            const int kk = s * 8;
            uint32_t bf[8][2];
#pragma unroll
            for (int ni = 0; ni < 8; ni++) {
                const uint2 b = *reinterpret_cast<const uint2*>(
                    Kb + (ni * 8 + gid) * AST + kk + 2 * tig);
                bf[ni][0] = b.x;
                bf[ni][1] = b.y;
            }
#pragma unroll
            for (int ni = 0; ni < 8; ni++)
                mma8(s4[ni], qf[s], bf[ni]);
        }

        // ---- causal mask (diagonal tile only; perm-token columns) ----
        if (kt == qt) {
            const int r0 = q0 + mrow + gid, r1 = r0 + 8;
            const int k0 = kt * 64;
#pragma unroll
            for (int ni = 0; ni < 8; ni++) {
                const int c0 = k0 + ni * 8 + tig;   // token for [0],[2]
                const int c1 = c0 + 4;              // token for [1],[3]
                if (c0 > r0) s4[ni][0] = -1e30f;
                if (c1 > r0) s4[ni][1] = -1e30f;
                if (c0 > r1) s4[ni][2] = -1e30f;
                if (c1 > r1) s4[ni][3] = -1e30f;
            }
        }

        // ---- register softmax (exp2 domain; rows warp-local) ----
        float mx0 = -1e30f, mx1 = -1e30f;
#pragma unroll
        for (int ni = 0; ni < 8; ni++) {
            mx0 = fmaxf(mx0, fmaxf(s4[ni][0], s4[ni][1]));
            mx1 = fmaxf(mx1, fmaxf(s4[ni][2], s4[ni][3]));
        }
        mx0 = fmaxf(mx0, __shfl_xor_sync(0xffffffffu, mx0, 1));
        mx0 = fmaxf(mx0, __shfl_xor_sync(0xffffffffu, mx0, 2));
        mx1 = fmaxf(mx1, __shfl_xor_sync(0xffffffffu, mx1, 1));
        mx1 = fmaxf(mx1, __shfl_xor_sync(0xffffffffu, mx1, 2));
        const float mn0 = fmaxf(m0r, mx0);
        const float mn1 = fmaxf(m1r, mx1);
        const float f0 = ex2(m0r - mn0);
        const float f1 = ex2(m1r - mn1);
        m0r = mn0; m1r = mn1;

        // P kept in registers (overwrite s4 with tf32-rounded probabilities)
        float sum0 = 0.f, sum1 = 0.f;
#pragma unroll
        for (int ni = 0; ni < 8; ni++) {
            const float e0 = ex2(s4[ni][0] - mn0);
            const float e1 = ex2(s4[ni][1] - mn0);
            const float e2 = ex2(s4[ni][2] - mn1);
            const float e3 = ex2(s4[ni][3] - mn1);
            sum0 += e0 + e1;
            sum1 += e2 + e3;
            s4[ni][0] = __uint_as_float(tf32r(e0));
            s4[ni][1] = __uint_as_float(tf32r(e1));
            s4[ni][2] = __uint_as_float(tf32r(e2));
            s4[ni][3] = __uint_as_float(tf32r(e3));
        }
        sum0 += __shfl_xor_sync(0xffffffffu, sum0, 1);
        sum0 += __shfl_xor_sync(0xffffffffu, sum0, 2);
        sum1 += __shfl_xor_sync(0xffffffffu, sum1, 1);
        sum1 += __shfl_xor_sync(0xffffffffu, sum1, 2);
        l0 = l0 * f0 + sum0;
        l1 = l1 * f1 + sum1;

#pragma unroll
        for (int ni = 0; ni < 8; ni++) {
            o[ni][0] *= f0; o[ni][1] *= f0;
            o[ni][2] *= f1; o[ni][3] *= f1;
        }

        // ---- O += P * V; A-frag = register rename of s4 ----
        const uint32_t* Vb = Vsb[cur];
#pragma unroll
        for (int s = 0; s < 8; s++) {
            const int kk = s * 8;
            uint32_t af[4];
            af[0] = __float_as_uint(s4[s][0]);  // k=tig,   row gid
            af[1] = __float_as_uint(s4[s][2]);  // k=tig,   row gid+8
            af[2] = __float_as_uint(s4[s][1]);  // k=tig+4, row gid
            af[3] = __float_as_uint(s4[s][3]);  // k=tig+4, row gid+8
            uint32_t bf[8][2];
#pragma unroll
            for (int ni = 0; ni < 8; ni++) {
                const uint32_t* q = Vb + (kk + tig) * AST + ni * 8 + gid;
                bf[ni][0] = q[0];
                bf[ni][1] = q[4 * AST];
            }
#pragma unroll
            for (int ni = 0; ni < 8; ni++)
                mma8(o[ni], af, bf[ni]);
        }
        __syncthreads();
    }

    // ---- finalize (cols = perm head positions, matching o_proj input) ----
    {
        const float inv0 = 1.f / l0;
        const float inv1 = 1.f / l1;
        const int r0 = q0 + mrow + gid;
        uint32_t* Ou = (uint32_t*)(Og + base);
#pragma unroll
        for (int ni = 0; ni < 8; ni++) {
            const int cc = ni * 8 + 2 * tig;
            uint2 oa, ob;
            oa.x = tf32r(o[ni][0] * inv0);
            oa.y = tf32r(o[ni][1] * inv0);
            ob.x = tf32r(o[ni][2] * inv1);
            ob.y = tf32r(o[ni][3] * inv1);
            *reinterpret_cast<uint2*>(Ou + (size_t)r0 * HDc + cc) = oa;
            *reinterpret_cast<uint2*>(Ou + (size_t)(r0 + 8) * HDc + cc) = ob;
        }
    }
}

// ---------------------------------------------------------------------------
extern "C" void kernel_launch(void* const* d_in, const int* in_sizes, int n_in,
                              void* d_out, int out_size)
{
    const float* q  = (const float*)d_in[0];
    const float* k  = (const float*)d_in[1];
    const float* v  = (const float*)d_in[2];
    // d_in[3] = mask (tril; causality applied analytically)
    const float* Wq = (const float*)d_in[4];
    const float* bq = (const float*)d_in[5];
    const float* Wk = (const float*)d_in[6];
    const float* bk = (const float*)d_in[7];
    const float* Wv = (const float*)d_in[8];
    const float* bv = (const float*)d_in[9];
    const float* Wo = (const float*)d_in[10];
    const float* bo = (const float*)d_in[11];
    float* out = (float*)d_out;

    float *qh, *kh, *vh, *ao, *qt, *kt, *vt, *wq, *wk, *wv, *wo;
    cudaGetSymbolAddress((void**)&qh, g_qh);
    cudaGetSymbolAddress((void**)&kh, g_kh);
    cudaGetSymbolAddress((void**)&vh, g_vh);
    cudaGetSymbolAddress((void**)&ao, g_ao);
    cudaGetSymbolAddress((void**)&qt, g_qt);
    cudaGetSymbolAddress((void**)&kt, g_kt);
    cudaGetSymbolAddress((void**)&vt, g_vt);
    cudaGetSymbolAddress((void**)&wq, g_wq);
    cudaGetSymbolAddress((void**)&wk, g_wk);
    cudaGetSymbolAddress((void**)&wv, g_wv);
    cudaGetSymbolAddress((void**)&wo, g_wo);

    static int cfg = 0;
    if (!cfg) {
        cudaFuncSetAttribute(qkv_proj,
            cudaFuncAttributeMaxDynamicSharedMemorySize, PROJ_SMEM);
        cudaFuncSetAttribute(o_proj,
            cudaFuncAttributeMaxDynamicSharedMemorySize, PROJ_SMEM);
        cudaFuncSetAttribute(attn2,
            cudaFuncAttributeMaxDynamicSharedMemorySize, ATT_SMEM);
        cfg = 1;
    }

    // tf32 + perm-k conversion, one launch
    const int blocks_x = (Mrows * DIMd / 8 + 255) / 256;  // 2048
    cvt_all<<<dim3(blocks_x, 1, 7), 256>>>(
        (const float4*)q, (const float4*)k, (const float4*)v,
        (const float4*)Wq, (const float4*)Wk, (const float4*)Wv, (const float4*)Wo,
        (float4*)qt, (float4*)kt, (float4*)vt,
        (float4*)wq, (float4*)wk, (float4*)wv, (float4*)wo);

    // Fused QKV projections (Q pre-scaled by ATTN_SCALE*log2e in epilogue)
    qkv_proj<<<dim3(DIMd / 128, Mrows / 128, 3), 256, PROJ_SMEM>>>(
        qt, kt, vt, wq, wk, wv, bq, bk, bv, qh, kh, vh);

    // Attention: 64 q-rows per CTA, heavy tiles first
    attn2<<<dim3(Nn / 64, Bb * Hh), 128, ATT_SMEM>>>(qh, kh, vh, ao);

    // Output projection
    o_proj<<<dim3(DIMd / 128, Mrows / 128), 256, PROJ_SMEM>>>(ao, wo, bo, out);
}

// round 15
// speedup vs baseline: 1.1742x; 1.0670x over previous
#include <cuda_runtime.h>
#include <math.h>
#include <stdint.h>

constexpr int Bb   = 2;
constexpr int Hh   = 16;
constexpr int Nn   = 2048;
constexpr int HDc  = 64;
constexpr int DIMd = 1024;
constexpr int Mrows = Bb * Nn;       // 4096
constexpr float ATTN_SCALE = 0.125f;
constexpr float LOG2E = 1.44269504088896340736f;

// k-group permutation: storage position 2t holds logical k t, 2t+1 holds t+4.
// In attention, K tile token ROWS are stored permuted => S cols land in
// perm-token order => PV A-frag is a register rename of softmax output.
// Softmax runs in the exp2 domain (log2e folded into the Q projection scale).

// Scratch buffers
__device__ float g_qh[Bb * Hh * Nn * HDc];   // Q heads (tf32, perm, pre-scaled by s*log2e)
__device__ float g_kh[Bb * Hh * Nn * HDc];   // K heads (tf32, perm head dim)
__device__ float g_vh[Bb * Hh * Nn * HDc];   // V heads (tf32, perm head dim)
__device__ float g_ao[Bb * Hh * Nn * HDc];   // attn out (tf32, perm head dim)
__device__ float g_qt[Mrows * DIMd];         // tf32 perm-k copies of inputs
__device__ float g_kt[Mrows * DIMd];
__device__ float g_vt[Mrows * DIMd];
__device__ float g_wq[DIMd * DIMd];          // tf32 perm-k copies of weights
__device__ float g_wk[DIMd * DIMd];
__device__ float g_wv[DIMd * DIMd];
__device__ float g_wo[DIMd * DIMd];

__device__ __forceinline__ uint32_t tf32r(float x) {
    uint32_t y;
    asm("cvt.rna.tf32.f32 %0, %1;" : "=r"(y) : "f"(x));
    return y;
}

__device__ __forceinline__ float ex2(float x) {
    float y;
    asm("ex2.approx.f32 %0, %1;" : "=f"(y) : "f"(x));
    return y;
}

__device__ __forceinline__ void mma8(float* d, const uint32_t* a, const uint32_t* b) {
    asm volatile(
        "mma.sync.aligned.m16n8k8.row.col.f32.tf32.tf32.f32 "
        "{%0,%1,%2,%3}, {%4,%5,%6,%7}, {%8,%9}, {%0,%1,%2,%3};\n"
        : "+f"(d[0]), "+f"(d[1]), "+f"(d[2]), "+f"(d[3])
        : "r"(a[0]), "r"(a[1]), "r"(a[2]), "r"(a[3]), "r"(b[0]), "r"(b[1]));
}

__device__ __forceinline__ void cp16(uint32_t daddr, const void* src) {
    asm volatile("cp.async.cg.shared.global [%0], [%1], 16;\n"
                 :: "r"(daddr), "l"(src));
}
__device__ __forceinline__ void cp_commit() {
    asm volatile("cp.async.commit_group;\n");
}
template <int N>
__device__ __forceinline__ void cp_wait() {
    asm volatile("cp.async.wait_group %0;\n" :: "n"(N));
}

// ---------------------------------------------------------------------------
// Fused tf32 (RNA) conversion + k-group permute (one launch).
// ---------------------------------------------------------------------------
__global__ __launch_bounds__(256) void cvt_all(
    const float4* q, const float4* k, const float4* v,
    const float4* wq, const float4* wk, const float4* wv, const float4* wo,
    float4* qt, float4* kt, float4* vt,
    float4* dwq, float4* dwk, float4* dwv, float4* dwo)
{
    const int z = blockIdx.z;
    const int n8 = (z < 3) ? (Mrows * DIMd / 8) : (DIMd * DIMd / 8);
    const int i = blockIdx.x * 256 + threadIdx.x;
    if (i >= n8) return;
    const float4* s;
    float4* d;
    switch (z) {
        case 0: s = q;  d = qt;  break;
        case 1: s = k;  d = kt;  break;
        case 2: s = v;  d = vt;  break;
        case 3: s = wq; d = dwq; break;
        case 4: s = wk; d = dwk; break;
        case 5: s = wv; d = dwv; break;
        default: s = wo; d = dwo; break;
    }
    const float4 a = s[2 * i];       // logical k 0..3
    const float4 b = s[2 * i + 1];   // logical k 4..7
    float4 o0, o1;
    o0.x = __uint_as_float(tf32r(a.x)); o0.y = __uint_as_float(tf32r(b.x));
    o0.z = __uint_as_float(tf32r(a.y)); o0.w = __uint_as_float(tf32r(b.y));
    o1.x = __uint_as_float(tf32r(a.z)); o1.y = __uint_as_float(tf32r(b.z));
    o1.z = __uint_as_float(tf32r(a.w)); o1.w = __uint_as_float(tf32r(b.w));
    d[2 * i]     = o0;
    d[2 * i + 1] = o1;
}

// ---------------------------------------------------------------------------
// Projection GEMM (proven): 128x128x32 tiles, 2-stage cp.async double buffer
// {issue(kt+1); wait<1>; sync; mma; sync}, 81.9KB smem,
// __launch_bounds__(256,2) -> 2 CTAs/SM, perm-k LDS.64 fragments.
// ---------------------------------------------------------------------------
constexpr int SKA = 40;                        // smem k-stride words
constexpr int PROJ_SMEM = 4 * 128 * SKA * 4;   // 81920 B

template <bool SPLIT_IN, bool SPLIT_OUT, bool ROUND>
__device__ __forceinline__ void proj_body(
    const float* __restrict__ A, const float* __restrict__ W,
    const float* __restrict__ bias, float* __restrict__ C, float scale,
    float* smf)
{
    const int m0 = blockIdx.y * 128, n0 = blockIdx.x * 128;
    const int tid = threadIdx.x;
    const int w = tid >> 5, lane = tid & 31;
    const int gid = lane >> 2, tig = lane & 3;
    const int mbase = (w & 1) * 64;
    const int nbase = (w >> 1) * 32;

    const uint32_t* Asb[2] = {(const uint32_t*)smf,
                              (const uint32_t*)smf + 128 * SKA};
    const uint32_t* Wsb[2] = {(const uint32_t*)smf + 2 * 128 * SKA,
                              (const uint32_t*)smf + 3 * 128 * SKA};
    const uint32_t su = (uint32_t)__cvta_generic_to_shared(smf);
    const uint32_t asu[2] = {su, su + 128 * SKA * 4};
    const uint32_t wsu[2] = {su + 2 * 128 * SKA * 4, su + 3 * 128 * SKA * 4};

    auto load_tiles = [&](int kt, int buf) {
        const int k0 = kt * 32;
#pragma unroll
        for (int t = 0; t < 4; t++) {
            const int idx = tid + t * 256;
            const int r = idx >> 3, c = (idx & 7) << 2;
            const float* ap;
            if (SPLIT_IN) {
                const int gm = m0 + r, gk = k0 + c;
                const int b = gm >> 11, tok = gm & (Nn - 1);
                const int h = gk >> 6, cc = gk & 63;
                ap = A + ((size_t)((b * Hh + h) * Nn + tok)) * HDc + cc;
            } else {
                ap = A + (size_t)(m0 + r) * DIMd + k0 + c;
            }
            cp16(asu[buf] + (r * SKA + c) * 4, ap);
            cp16(wsu[buf] + (r * SKA + c) * 4,
                 W + (size_t)(n0 + r) * DIMd + k0 + c);
        }
        cp_commit();
    };

    float c[4][4][4];
#pragma unroll
    for (int mi = 0; mi < 4; mi++)
#pragma unroll
        for (int ni = 0; ni < 4; ni++)
#pragma unroll
            for (int u = 0; u < 4; u++) c[mi][ni][u] = 0.f;

    load_tiles(0, 0);
    constexpr int ITERS = DIMd / 32;  // 32
    for (int kt = 0; kt < ITERS; kt++) {
        const int cur = kt & 1;
        if (kt + 1 < ITERS) { load_tiles(kt + 1, cur ^ 1); cp_wait<1>(); }
        else                { cp_wait<0>(); }
        __syncthreads();

        const uint32_t* Ab = Asb[cur];
        const uint32_t* Wb = Wsb[cur];
#pragma unroll
        for (int kk = 0; kk < 32; kk += 8) {
            uint32_t af[4][4];
#pragma unroll
            for (int mi = 0; mi < 4; mi++) {
                const int row = mbase + mi * 16 + gid;
                const uint2 a0 = *reinterpret_cast<const uint2*>(
                    Ab + row * SKA + kk + 2 * tig);
                const uint2 a1 = *reinterpret_cast<const uint2*>(
                    Ab + (row + 8) * SKA + kk + 2 * tig);
                af[mi][0] = a0.x; af[mi][1] = a1.x;
                af[mi][2] = a0.y; af[mi][3] = a1.y;
            }
            uint32_t bf[4][2];
#pragma unroll
            for (int ni = 0; ni < 4; ni++) {
                const uint2 b = *reinterpret_cast<const uint2*>(
                    Wb + (nbase + ni * 8 + gid) * SKA + kk + 2 * tig);
                bf[ni][0] = b.x;
                bf[ni][1] = b.y;
            }
#pragma unroll
            for (int mi = 0; mi < 4; mi++)
#pragma unroll
                for (int ni = 0; ni < 4; ni++)
                    mma8(c[mi][ni], af[mi], bf[ni]);
        }
        __syncthreads();
    }

    // Epilogue. Logical cols 2tig, 2tig+1 -> permuted head positions p0, p0+2.
    const int p0 = (tig < 2) ? 4 * tig : 4 * tig - 7;
#pragma unroll
    for (int mi = 0; mi < 4; mi++) {
#pragma unroll
        for (int ni = 0; ni < 4; ni++) {
            const int nlog = n0 + nbase + ni * 8 + 2 * tig;
            const float bx = bias[nlog], by = bias[nlog + 1];
#pragma unroll
            for (int hr = 0; hr < 2; hr++) {
                const int m = m0 + mbase + mi * 16 + gid + hr * 8;
                float ox = (c[mi][ni][hr * 2 + 0] + bx) * scale;
                float oy = (c[mi][ni][hr * 2 + 1] + by) * scale;
                if (ROUND) {
                    ox = __uint_as_float(tf32r(ox));
                    oy = __uint_as_float(tf32r(oy));
                }
                if (SPLIT_OUT) {
                    const int b = m >> 11, tok = m & (Nn - 1);
                    const int np0 = n0 + nbase + ni * 8 + p0;
                    const int h = np0 >> 6;
                    float* dst = C + ((size_t)((b * Hh + h) * Nn + tok)) * HDc;
                    dst[np0 & 63]       = ox;
                    dst[(np0 + 2) & 63] = oy;
                } else {
                    float2 o; o.x = ox; o.y = oy;
                    *reinterpret_cast<float2*>(C + (size_t)m * DIMd + nlog) = o;
                }
            }
        }
    }
}

__global__ __launch_bounds__(256, 2) void qkv_proj(
    const float* aq, const float* ak, const float* av,
    const float* wq, const float* wk, const float* wv,
    const float* bq, const float* bk, const float* bv,
    float* cq, float* ck, float* cv)
{
    extern __shared__ float smf[];
    const int z = blockIdx.z;
    const float* A = (z == 0) ? aq : (z == 1) ? ak : av;
    const float* W = (z == 0) ? wq : (z == 1) ? wk : wv;
    const float* b = (z == 0) ? bq : (z == 1) ? bk : bv;
    float*       C = (z == 0) ? cq : (z == 1) ? ck : cv;
    // Q gets attn scale AND log2e folded in (softmax runs in exp2 domain)
    const float scale = (z == 0) ? ATTN_SCALE * LOG2E : 1.0f;
    proj_body<false, true, true>(A, W, b, C, scale, smf);
}

__global__ __launch_bounds__(256, 2) void o_proj(
    const float* A, const float* W, const float* b, float* C)
{
    extern __shared__ float smf[];
    proj_body<true, false, false>(A, W, b, C, 1.0f, smf);
}

// ---------------------------------------------------------------------------
// Causal flash attention: 64 q-rows/CTA, 128 threads (4 warps, 16x64 strips),
// register softmax (exp2 domain), heavy-first, K rows perm-stored, PV A-frag
// = register rename, no P smem. K double-buffered (2-tile lookahead),
// V SINGLE-buffered (issued right after prior PV, hidden behind S+softmax).
// Smem 55.3KB -> 4 CTAs/SM.
// ---------------------------------------------------------------------------
constexpr int AST = 72;  // smem row stride (words)
constexpr int ATT_SMEM = 3 * 64 * AST * 4;  // 2xK + 1xV = 55296 B

__global__ __launch_bounds__(128, 4) void attn2(
    const float* __restrict__ Qg, const float* __restrict__ Kg,
    const float* __restrict__ Vg, float* __restrict__ Og)
{
    extern __shared__ float smf[];
    const uint32_t su = (uint32_t)__cvta_generic_to_shared(smf);
    const uint32_t ksu[2] = {su, su + 64 * AST * 4};
    const uint32_t vsu    = su + 2 * 64 * AST * 4;
    const uint32_t* Ksb[2] = {(const uint32_t*)smf,
                              (const uint32_t*)smf + 64 * AST};
    const uint32_t* Vsb    = (const uint32_t*)smf + 2 * 64 * AST;

    const int bh = blockIdx.y;
    const int qt = (gridDim.x - 1) - blockIdx.x;   // heavy-first
    const int q0 = qt * 64;
    const size_t base = (size_t)bh * Nn * HDc;

    const int tid = threadIdx.x;
    const int w = tid >> 5, lane = tid & 31;
    const int gid = lane >> 2, tig = lane & 3;
    const int mrow = w * 16;

    auto issueK = [&](int t_kt, int buf) {
        const float* Kb = Kg + base + (size_t)(t_kt * 64) * HDc;
#pragma unroll
        for (int t = 0; t < 8; t++) {
            const int idx = tid + t * 128;
            const int r = idx >> 4, cc = (idx & 15) << 2;
            // K rows stored at permuted positions within each 8-token group
            const int pr = (r & ~7) | ((r & 3) << 1) | ((r >> 2) & 1);
            cp16(ksu[buf] + (pr * AST + cc) * 4, Kb + r * HDc + cc);
        }
        cp_commit();
    };
    auto issueV = [&](int t_kt) {
        const float* Vb = Vg + base + (size_t)(t_kt * 64) * HDc;
#pragma unroll
        for (int t = 0; t < 8; t++) {
            const int idx = tid + t * 128;
            const int r = idx >> 4, cc = (idx & 15) << 2;
            cp16(vsu + (r * AST + cc) * 4, Vb + r * HDc + cc);
        }
        cp_commit();
    };

    // Q fragments from perm-k qh: 64-bit pairs at 2tig
    uint32_t qf[8][4];
    {
        const uint32_t* Qu = (const uint32_t*)(Qg + base) +
                             (size_t)(q0 + mrow + gid) * HDc;
#pragma unroll
        for (int s = 0; s < 8; s++) {
            const uint2 u0 = *reinterpret_cast<const uint2*>(Qu + s * 8 + 2 * tig);
            const uint2 u1 = *reinterpret_cast<const uint2*>(Qu + 8 * HDc + s * 8 + 2 * tig);
            qf[s][0] = u0.x; qf[s][1] = u1.x;
            qf[s][2] = u0.y; qf[s][3] = u1.y;
        }
    }

    float o[8][4];
#pragma unroll
    for (int ni = 0; ni < 8; ni++)
#pragma unroll
        for (int u = 0; u < 4; u++) o[ni][u] = 0.f;
    float m0r = -1e30f, m1r = -1e30f, l0 = 0.f, l1 = 0.f;

    issueK(0, 0);
    issueV(0);
    if (qt > 0) issueK(1, 1);

    for (int kt = 0; kt <= qt; kt++) {
        const int cur = kt & 1;
        // K(kt), V(kt) are the oldest outstanding groups; K(kt+1) (if issued)
        // is the newest -> wait<1> makes this tile resident while keeping the
        // K lookahead in flight.
        if (kt < qt) cp_wait<1>();
        else         cp_wait<0>();
        __syncthreads();

        // ---- S = Q K^T (16x64 per warp); LDS.64 K frags; S in log2 units ----
        float s4[8][4];
#pragma unroll
        for (int ni = 0; ni < 8; ni++)
#pragma unroll
            for (int u = 0; u < 4; u++) s4[ni][u] = 0.f;

        const uint32_t* Kb = Ksb[cur];
#pragma unroll
        for (int s = 0; s < 8; s++) {
            const int kk = s * 8;
            uint32_t bf[8][2];
#pragma unroll
            for (int ni = 0; ni < 8; ni++) {
                const uint2 b = *reinterpret_cast<const uint2*>(
                    Kb + (ni * 8 + gid) * AST + kk + 2 * tig);
                bf[ni][0] = b.x;
                bf[ni][1] = b.y;
            }
#pragma unroll
            for (int ni = 0; ni < 8; ni++)
                mma8(s4[ni], qf[s], bf[ni]);
        }

        // ---- causal mask (diagonal tile only; perm-token columns) ----
        if (kt == qt) {
            const int r0 = q0 + mrow + gid, r1 = r0 + 8;
            const int k0 = kt * 64;
#pragma unroll
            for (int ni = 0; ni < 8; ni++) {
                const int c0 = k0 + ni * 8 + tig;   // token for [0],[2]
                const int c1 = c0 + 4;              // token for [1],[3]
                if (c0 > r0) s4[ni][0] = -1e30f;
                if (c1 > r0) s4[ni][1] = -1e30f;
                if (c0 > r1) s4[ni][2] = -1e30f;
                if (c1 > r1) s4[ni][3] = -1e30f;
            }
        }

        // ---- register softmax (exp2 domain; rows warp-local) ----
        float mx0 = -1e30f, mx1 = -1e30f;
#pragma unroll
        for (int ni = 0; ni < 8; ni++) {
            mx0 = fmaxf(mx0, fmaxf(s4[ni][0], s4[ni][1]));
            mx1 = fmaxf(mx1, fmaxf(s4[ni][2], s4[ni][3]));
        }
        mx0 = fmaxf(mx0, __shfl_xor_sync(0xffffffffu, mx0, 1));
        mx0 = fmaxf(mx0, __shfl_xor_sync(0xffffffffu, mx0, 2));
        mx1 = fmaxf(mx1, __shfl_xor_sync(0xffffffffu, mx1, 1));
        mx1 = fmaxf(mx1, __shfl_xor_sync(0xffffffffu, mx1, 2));
        const float mn0 = fmaxf(m0r, mx0);
        const float mn1 = fmaxf(m1r, mx1);
        const float f0 = ex2(m0r - mn0);
        const float f1 = ex2(m1r - mn1);
        m0r = mn0; m1r = mn1;

        // P kept in registers (overwrite s4 with tf32-rounded probabilities)
        float sum0 = 0.f, sum1 = 0.f;
#pragma unroll
        for (int ni = 0; ni < 8; ni++) {
            const float e0 = ex2(s4[ni][0] - mn0);
            const float e1 = ex2(s4[ni][1] - mn0);
            const float e2 = ex2(s4[ni][2] - mn1);
            const float e3 = ex2(s4[ni][3] - mn1);
            sum0 += e0 + e1;
            sum1 += e2 + e3;
            s4[ni][0] = __uint_as_float(tf32r(e0));
            s4[ni][1] = __uint_as_float(tf32r(e1));
            s4[ni][2] = __uint_as_float(tf32r(e2));
            s4[ni][3] = __uint_as_float(tf32r(e3));
        }
        sum0 += __shfl_xor_sync(0xffffffffu, sum0, 1);
        sum0 += __shfl_xor_sync(0xffffffffu, sum0, 2);
        sum1 += __shfl_xor_sync(0xffffffffu, sum1, 1);
        sum1 += __shfl_xor_sync(0xffffffffu, sum1, 2);
        l0 = l0 * f0 + sum0;
        l1 = l1 * f1 + sum1;

#pragma unroll
        for (int ni = 0; ni < 8; ni++) {
            o[ni][0] *= f0; o[ni][1] *= f0;
            o[ni][2] *= f1; o[ni][3] *= f1;
        }

        // ---- O += P * V; A-frag = register rename of s4 ----
#pragma unroll
        for (int s = 0; s < 8; s++) {
            const int kk = s * 8;
            uint32_t af[4];
            af[0] = __float_as_uint(s4[s][0]);  // k=tig,   row gid
            af[1] = __float_as_uint(s4[s][2]);  // k=tig,   row gid+8
            af[2] = __float_as_uint(s4[s][1]);  // k=tig+4, row gid
            af[3] = __float_as_uint(s4[s][3]);  // k=tig+4, row gid+8
            uint32_t bf[8][2];
#pragma unroll
            for (int ni = 0; ni < 8; ni++) {
                const uint32_t* q = Vsb + (kk + tig) * AST + ni * 8 + gid;
                bf[ni][0] = q[0];
                bf[ni][1] = q[4 * AST];
            }
#pragma unroll
            for (int ni = 0; ni < 8; ni++)
                mma8(o[ni], af, bf[ni]);
        }
        __syncthreads();   // all warps done with V buf + K buf cur

        if (kt < qt) {
            issueV(kt + 1);                       // lands during next S phase
            if (kt + 1 < qt) issueK(kt + 2, cur); // K 2-tile lookahead
        }
    }

    // ---- finalize (cols = perm head positions, matching o_proj input) ----
    {
        const float inv0 = 1.f / l0;
        const float inv1 = 1.f / l1;
        const int r0 = q0 + mrow + gid;
        uint32_t* Ou = (uint32_t*)(Og + base);
#pragma unroll
        for (int ni = 0; ni < 8; ni++) {
            const int cc = ni * 8 + 2 * tig;
            uint2 oa, ob;
            oa.x = tf32r(o[ni][0] * inv0);
            oa.y = tf32r(o[ni][1] * inv0);
            ob.x = tf32r(o[ni][2] * inv1);
            ob.y = tf32r(o[ni][3] * inv1);
            *reinterpret_cast<uint2*>(Ou + (size_t)r0 * HDc + cc) = oa;
            *reinterpret_cast<uint2*>(Ou + (size_t)(r0 + 8) * HDc + cc) = ob;
        }
    }
}

// ---------------------------------------------------------------------------
extern "C" void kernel_launch(void* const* d_in, const int* in_sizes, int n_in,
                              void* d_out, int out_size)
{
    const float* q  = (const float*)d_in[0];
    const float* k  = (const float*)d_in[1];
    const float* v  = (const float*)d_in[2];
    // d_in[3] = mask (tril; causality applied analytically)
    const float* Wq = (const float*)d_in[4];
    const float* bq = (const float*)d_in[5];
    const float* Wk = (const float*)d_in[6];
    const float* bk = (const float*)d_in[7];
    const float* Wv = (const float*)d_in[8];
    const float* bv = (const float*)d_in[9];
    const float* Wo = (const float*)d_in[10];
    const float* bo = (const float*)d_in[11];
    float* out = (float*)d_out;

    float *qh, *kh, *vh, *ao, *qt, *kt, *vt, *wq, *wk, *wv, *wo;
    cudaGetSymbolAddress((void**)&qh, g_qh);
    cudaGetSymbolAddress((void**)&kh, g_kh);
    cudaGetSymbolAddress((void**)&vh, g_vh);
    cudaGetSymbolAddress((void**)&ao, g_ao);
    cudaGetSymbolAddress((void**)&qt, g_qt);
    cudaGetSymbolAddress((void**)&kt, g_kt);
    cudaGetSymbolAddress((void**)&vt, g_vt);
    cudaGetSymbolAddress((void**)&wq, g_wq);
    cudaGetSymbolAddress((void**)&wk, g_wk);
    cudaGetSymbolAddress((void**)&wv, g_wv);
    cudaGetSymbolAddress((void**)&wo, g_wo);

    static int cfg = 0;
    if (!cfg) {
        cudaFuncSetAttribute(qkv_proj,
            cudaFuncAttributeMaxDynamicSharedMemorySize, PROJ_SMEM);
        cudaFuncSetAttribute(o_proj,
            cudaFuncAttributeMaxDynamicSharedMemorySize, PROJ_SMEM);
        cudaFuncSetAttribute(attn2,
            cudaFuncAttributeMaxDynamicSharedMemorySize, ATT_SMEM);
        cfg = 1;
    }

    // tf32 + perm-k conversion, one launch
    const int blocks_x = (Mrows * DIMd / 8 + 255) / 256;  // 2048
    cvt_all<<<dim3(blocks_x, 1, 7), 256>>>(
        (const float4*)q, (const float4*)k, (const float4*)v,
        (const float4*)Wq, (const float4*)Wk, (const float4*)Wv, (const float4*)Wo,
        (float4*)qt, (float4*)kt, (float4*)vt,
        (float4*)wq, (float4*)wk, (float4*)wv, (float4*)wo);

    // Fused QKV projections (Q pre-scaled by ATTN_SCALE*log2e in epilogue)
    qkv_proj<<<dim3(DIMd / 128, Mrows / 128, 3), 256, PROJ_SMEM>>>(
        qt, kt, vt, wq, wk, wv, bq, bk, bv, qh, kh, vh);

    // Attention: 64 q-rows per CTA, heavy tiles first, 4 CTAs/SM
    attn2<<<dim3(Nn / 64, Bb * Hh), 128, ATT_SMEM>>>(qh, kh, vh, ao);

    // Output projection
    o_proj<<<dim3(DIMd / 128, Mrows / 128), 256, PROJ_SMEM>>>(ao, wo, bo, out);
}